// round 12
// baseline (speedup 1.0000x reference)
#include <cuda_runtime.h>

// ---------------------------------------------------------------------------
// ScalarDotProductCriticNetworkV8 — multi-kernel SGEMM restructure (R12).
//
// R12 vs R11 (57.5us; gemm_aw 16us from per-chunk sync+LDG bubbles):
//   * gemm_kqc: register double-buffered (prefetch chunk c+1 into regs before
//     computing chunk c; STS after). 7 chunks, no exposed LDG.
//   * aw_attn: FUSED gemm_aw + attn_out. Full 32x256 av panel staged in smem
//     once (1 sync), 128-deep FMA loop with no mid-loop syncs; accumulators
//     -> smem; attention for the CTA's 2 batches runs in-place. g_aw round
//     trip and one kernel launch eliminated. Dynamic smem 69.6KB, phase-aliased.
//   * prep / tails_tanh byte-identical to R11 (known correct).
// ---------------------------------------------------------------------------

#define ULL unsigned long long

#define PACK2(d, lo, hi) asm("mov.b64 %0, {%1, %2};" : "=l"(d) : "f"(lo), "f"(hi))
#define UNPACK2(lo, hi, v) asm("mov.b64 {%0, %1}, %2;" : "=f"(lo), "=f"(hi) : "l"(v))
#define FMA2(acc, a, b) asm("fma.rn.f32x2 %0, %1, %2, %0;" : "+l"(acc) : "l"(a), "l"(b))
#define TANHA(y, x) asm("tanh.approx.f32 %0, %1;" : "=f"(y) : "f"(x))

// Weights (pre-transposed) and activations scratch.
__device__ float g_B1[112 * 384];    // [kk][col]: 0-127 WkT, 128-255 WqT, 256-383 WvT(states)
__device__ float g_Btail[16 * 128];  // [f][c] = Wv[c][112+f]
__device__ float g_W1T[128 * 64];    // [d][h]
__device__ float g_C[8192 * 384];    // row-major: k | q(scaled+biased) | cs(biased)
__device__ float g_av[8192 * 256];   // avo | avd

__global__ void prep(const float* __restrict__ Wk, const float* __restrict__ Wq,
                     const float* __restrict__ Wv, const float* __restrict__ W1) {
    int t = blockIdx.x * blockDim.x + threadIdx.x, S = gridDim.x * blockDim.x;
    for (int i = t; i < 112 * 384; i += S) {
        int kk = i / 384, col = i - kk * 384;
        float v;
        if (col < 128)      v = Wk[col * 112 + kk];
        else if (col < 256) v = Wq[(col - 128) * 112 + kk];
        else                v = Wv[(col - 256) * 128 + kk];
        g_B1[i] = v;
    }
    for (int i = t; i < 16 * 128; i += S) {
        int f = i >> 7, c = i & 127;
        g_Btail[i] = Wv[c * 128 + 112 + f];
    }
    for (int i = t; i < 128 * 64; i += S) {
        int d = i >> 6, h = i & 63;
        g_W1T[i] = W1[h * 128 + d];
    }
}

// ---- A1: C = states @ B1 (+bias, q-scale). grid (128, 3), block 256 ----
// Register double-buffered over 7 k-chunks of 16.
__global__ void __launch_bounds__(256) gemm_kqc(
    const float* __restrict__ states, const float* __restrict__ bk,
    const float* __restrict__ bq, const float* __restrict__ bv) {
    __shared__ float As[2][16][68];     // [buf][kk][row], 64 rows
    __shared__ float Bs[2][16][128];    // [buf][kk][col]
    const int tid = threadIdx.x;
    const int m0 = blockIdx.x * 64, n0 = blockIdx.y * 128;
    const int tr = tid >> 4, tc = tid & 15;
    const int arow = tid >> 2, akq = (tid & 3) * 4;
    const int brow0 = tid >> 5,        bcol0 = (tid & 31) * 4;
    const int brow1 = (256 + tid) >> 5, bcol1 = ((256 + tid) & 31) * 4;

    float4 apre, bpre0, bpre1;
    // prefetch + stage chunk 0
    apre  = *reinterpret_cast<const float4*>(states + (m0 + arow) * 112 + akq);
    bpre0 = *reinterpret_cast<const float4*>(g_B1 + brow0 * 384 + n0 + bcol0);
    bpre1 = *reinterpret_cast<const float4*>(g_B1 + brow1 * 384 + n0 + bcol1);
    As[0][akq + 0][arow] = apre.x; As[0][akq + 1][arow] = apre.y;
    As[0][akq + 2][arow] = apre.z; As[0][akq + 3][arow] = apre.w;
    *reinterpret_cast<float4*>(&Bs[0][brow0][bcol0]) = bpre0;
    *reinterpret_cast<float4*>(&Bs[0][brow1][bcol1]) = bpre1;
    __syncthreads();

    ULL acc[4][4];
#pragma unroll
    for (int r = 0; r < 4; r++)
#pragma unroll
        for (int c = 0; c < 4; c++) acc[r][c] = 0ull;

    for (int ch = 0; ch < 7; ch++) {
        const int buf = ch & 1;
        if (ch < 6) {
            int k0n = (ch + 1) * 16;
            apre  = *reinterpret_cast<const float4*>(states + (m0 + arow) * 112 + k0n + akq);
            bpre0 = *reinterpret_cast<const float4*>(g_B1 + (k0n + brow0) * 384 + n0 + bcol0);
            bpre1 = *reinterpret_cast<const float4*>(g_B1 + (k0n + brow1) * 384 + n0 + bcol1);
        }
#pragma unroll
        for (int kk = 0; kk < 16; kk++) {
            float4 a  = *reinterpret_cast<const float4*>(&As[buf][kk][tr * 4]);
            float4 b0 = *reinterpret_cast<const float4*>(&Bs[buf][kk][tc * 4]);
            float4 b1 = *reinterpret_cast<const float4*>(&Bs[buf][kk][64 + tc * 4]);
            ULL bu[4];
            PACK2(bu[0], b0.x, b0.y); PACK2(bu[1], b0.z, b0.w);
            PACK2(bu[2], b1.x, b1.y); PACK2(bu[3], b1.z, b1.w);
            float ar[4] = {a.x, a.y, a.z, a.w};
#pragma unroll
            for (int r = 0; r < 4; r++) {
                ULL a2; PACK2(a2, ar[r], ar[r]);
                FMA2(acc[r][0], a2, bu[0]); FMA2(acc[r][1], a2, bu[1]);
                FMA2(acc[r][2], a2, bu[2]); FMA2(acc[r][3], a2, bu[3]);
            }
        }
        if (ch < 6) {
            const int nb = buf ^ 1;
            As[nb][akq + 0][arow] = apre.x; As[nb][akq + 1][arow] = apre.y;
            As[nb][akq + 2][arow] = apre.z; As[nb][akq + 3][arow] = apre.w;
            *reinterpret_cast<float4*>(&Bs[nb][brow0][bcol0]) = bpre0;
            *reinterpret_cast<float4*>(&Bs[nb][brow1][bcol1]) = bpre1;
        }
        __syncthreads();
    }

    const float* bias = (blockIdx.y == 0) ? bk : (blockIdx.y == 1) ? bq : bv;
    const float qs = (blockIdx.y == 1) ? 0.08838834764831845f : 1.0f;
    float ba[4], bb[4];
#pragma unroll
    for (int c = 0; c < 4; c++) { ba[c] = bias[tc * 4 + c]; bb[c] = bias[64 + tc * 4 + c]; }
#pragma unroll
    for (int r = 0; r < 4; r++) {
        float o[8];
        UNPACK2(o[0], o[1], acc[r][0]); UNPACK2(o[2], o[3], acc[r][1]);
        UNPACK2(o[4], o[5], acc[r][2]); UNPACK2(o[6], o[7], acc[r][3]);
        float* cp = g_C + (m0 + tr * 4 + r) * 384 + n0;
        *reinterpret_cast<float4*>(cp + tc * 4) =
            make_float4((o[0] + ba[0]) * qs, (o[1] + ba[1]) * qs,
                        (o[2] + ba[2]) * qs, (o[3] + ba[3]) * qs);
        *reinterpret_cast<float4*>(cp + 64 + tc * 4) =
            make_float4((o[4] + bb[0]) * qs, (o[5] + bb[1]) * qs,
                        (o[6] + bb[2]) * qs, (o[7] + bb[3]) * qs);
    }
}

// ---- A2: avo/avd = tanh(cs + tail). grid 256, block 256 (unchanged) ----
__global__ void __launch_bounds__(256) tails_tanh(
    const float* __restrict__ actions, const float* __restrict__ policies) {
    __shared__ float actT[16][36], polT[16][36];   // [f][rr], 32 rows
    const int tid = threadIdx.x;
    const int r0 = blockIdx.x * 32;
#pragma unroll
    for (int w = 0; w < 2; w++) {
        int idx = tid + 256 * w;                   // 0..511
        int rr = idx >> 4, f = idx & 15;
        actT[f][rr] = actions[(r0 + rr) * 16 + f];
        polT[f][rr] = policies[(r0 + rr) * 16 + f];
    }
    __syncthreads();
    const int c = tid & 127, g = tid >> 7;         // 16 rows each
    float wv[16];
#pragma unroll
    for (int f = 0; f < 16; f++) wv[f] = g_Btail[f * 128 + c];
    for (int rr = g * 16; rr < g * 16 + 16; rr++) {
        float cs = g_C[(r0 + rr) * 384 + 256 + c];
        float ao = cs, ad = cs;
#pragma unroll
        for (int f = 0; f < 16; f++) {
            ao = fmaf(actT[f][rr], wv[f], ao);
            ad = fmaf(polT[f][rr], wv[f], ad);
        }
        float to, td; TANHA(to, ao); TANHA(td, ad);
        g_av[(r0 + rr) * 256 + c] = to;
        g_av[(r0 + rr) * 256 + 128 + c] = td;
    }
}

// ---- A3+B fused: [AW1|AdW1] = av @ W1T, then attention+output for the
//      CTA's 2 batches. grid 256, block 256, dynamic smem 69632B. ----
// Dynamic smem layout (floats), two aliased phases:
//   phase 1: WS  @0     (128*64 = 8192)     W1T [d][h]
//            AST @8192  (256*36 = 9216)     av transposed [k][row], 32 rows
//   phase 2: KS  @0     (32*132 = 4224)
//            QS  @4224  (32*132 = 4224)
//            AWS @8448  (32*136 = 4352)     [row][ AW1(0..63) | AdW1(64..127) ]
//            SW1 @12800 (32*64  = 2048)
//            WT  @14848 (32*17  = 544)
//            W2S @15392 (64)
#define DSM_FLOATS 17408
#define DSM_BYTES  (DSM_FLOATS * 4)

__global__ void __launch_bounds__(256, 2) aw_attn(
    const float* __restrict__ W2, float* __restrict__ out, int out_size) {
    extern __shared__ float dsm[];
    float* WS  = dsm;
    float* AST = dsm + 8192;
    float* KS  = dsm;
    float* QS  = dsm + 4224;
    float* AWS = dsm + 8448;
    float* SW1 = dsm + 12800;
    float* WT  = dsm + 14848;
    float* W2S = dsm + 15392;

    const int tid = threadIdx.x;
    const int m0 = blockIdx.x * 32;    // 32 rows = 2 batches
    const int b0 = blockIdx.x * 2;

    // ---- phase 1a: stage W1T and the full 32x256 av panel (transposed) ----
#pragma unroll
    for (int w = 0; w < 8; w++) {
        int f4i = w * 256 + tid;                   // 0..2047
        int d = f4i >> 4, hh = (f4i & 15) * 4;
        *reinterpret_cast<float4*>(WS + d * 64 + hh) =
            *reinterpret_cast<const float4*>(g_W1T + d * 64 + hh);
    }
#pragma unroll
    for (int w = 0; w < 8; w++) {
        int f4i = w * 256 + tid;                   // 0..2047 (32 rows x 64 f4)
        int row = f4i >> 6, k4 = (f4i & 63) * 4;
        float4 v = *reinterpret_cast<const float4*>(g_av + (m0 + row) * 256 + k4);
        AST[(k4 + 0) * 36 + row] = v.x; AST[(k4 + 1) * 36 + row] = v.y;
        AST[(k4 + 2) * 36 + row] = v.z; AST[(k4 + 3) * 36 + row] = v.w;
    }
    __syncthreads();

    // ---- phase 1b: GEMM, no mid-loop syncs ----
    const int tc = tid & 31, tr = tid >> 5;        // tr = warp id (0..7)
    const int sel = tc >> 4, h = (tc & 15) * 4;
    ULL acc[4][2];
#pragma unroll
    for (int r = 0; r < 4; r++) { acc[r][0] = 0ull; acc[r][1] = 0ull; }
#pragma unroll 8
    for (int kk = 0; kk < 128; kk++) {
        float4 a = *reinterpret_cast<const float4*>(AST + (sel * 128 + kk) * 36 + tr * 4);
        float4 b = *reinterpret_cast<const float4*>(WS + kk * 64 + h);
        ULL bu0, bu1;
        PACK2(bu0, b.x, b.y); PACK2(bu1, b.z, b.w);
        float ar[4] = {a.x, a.y, a.z, a.w};
#pragma unroll
        for (int r = 0; r < 4; r++) {
            ULL a2; PACK2(a2, ar[r], ar[r]);
            FMA2(acc[r][0], a2, bu0); FMA2(acc[r][1], a2, bu1);
        }
    }
    __syncthreads();   // all reads of WS/AST done before aliased writes below

    // ---- phase 2a: spill accumulators, load k/q and W2 ----
#pragma unroll
    for (int r = 0; r < 4; r++) {
        float o[4];
        UNPACK2(o[0], o[1], acc[r][0]);
        UNPACK2(o[2], o[3], acc[r][1]);
        *reinterpret_cast<float4*>(AWS + (tr * 4 + r) * 136 + sel * 64 + h) =
            make_float4(o[0], o[1], o[2], o[3]);
    }
#pragma unroll
    for (int w = 0; w < 4; w++) {
        int f4i = w * 256 + tid;                   // 0..1023 (32 rows x 32 f4)
        int rr = f4i >> 5, c4 = (f4i & 31) * 4;
        *reinterpret_cast<float4*>(KS + rr * 132 + c4) =
            *reinterpret_cast<const float4*>(g_C + (m0 + rr) * 384 + c4);
        *reinterpret_cast<float4*>(QS + rr * 132 + c4) =
            *reinterpret_cast<const float4*>(g_C + (m0 + rr) * 384 + 128 + c4);
    }
    if (tid < 64) W2S[tid] = W2[tid];
    __syncthreads();

    // ---- phase 2b: scores + softmax over i (16-lane shfl groups) ----
#pragma unroll
    for (int s2 = 0; s2 < 2; s2++) {
        int id = tid + 256 * s2;                   // 0..511
        int sbl = id >> 8, j = (id >> 4) & 15, i = id & 15;
        const float4* qp = reinterpret_cast<const float4*>(QS + (sbl * 16 + i) * 132);
        const float4* kp = reinterpret_cast<const float4*>(KS + (sbl * 16 + j) * 132);
        float s0 = 0.f, s1 = 0.f, s2f = 0.f, s3 = 0.f;
#pragma unroll 8
        for (int d4 = 0; d4 < 32; d4++) {
            float4 qv = qp[d4], kv = kp[d4];
            s0 = fmaf(qv.x, kv.x, s0); s1 = fmaf(qv.y, kv.y, s1);
            s2f = fmaf(qv.z, kv.z, s2f); s3 = fmaf(qv.w, kv.w, s3);
        }
        float sc = (s0 + s1) + (s2f + s3);
        float m = sc;
#pragma unroll
        for (int o = 8; o; o >>= 1) m = fmaxf(m, __shfl_xor_sync(0xffffffffu, m, o));
        float e = __expf(sc - m);
        float sum = e;
#pragma unroll
        for (int o = 8; o; o >>= 1) sum += __shfl_xor_sync(0xffffffffu, sum, o);
        WT[(sbl * 16 + j) * 17 + i] = e / sum;
    }
    __syncthreads();

    // ---- phase 2c: SW1[ag,h] = sum_i WT[ag,i] * AW1[blr+i,h] ----
    {
        int hh = tid & 63, g2 = tid >> 6, a0 = g2 * 8;   // a0 in {0,8,16,24}
        int blr = (a0 >> 4) * 16;
        float accs[8] = {};
#pragma unroll
        for (int i = 0; i < 16; i++) {
            float aw_ = AWS[(blr + i) * 136 + hh];
#pragma unroll
            for (int aa = 0; aa < 8; aa++)
                accs[aa] = fmaf(WT[(a0 + aa) * 17 + i], aw_, accs[aa]);
        }
#pragma unroll
        for (int aa = 0; aa < 8; aa++) SW1[(a0 + aa) * 64 + hh] = accs[aa];
    }
    __syncthreads();

    // ---- phase 2d: outputs ----
#pragma unroll
    for (int s2 = 0; s2 < 2; s2++) {
        int id = tid + 256 * s2;                   // 0..511
        int sbl = id >> 8, r2 = id & 255;
        int a = r2 >> 4, j = r2 & 15;
        int ag = sbl * 16 + a, jg = sbl * 16 + j;
        float waj = WT[ag * 17 + j];
        const float4* adp = reinterpret_cast<const float4*>(AWS + jg * 136 + 64);
        const float4* awp = reinterpret_cast<const float4*>(AWS + jg * 136);
        const float4* swp = reinterpret_cast<const float4*>(SW1 + ag * 64);
        const float4* w2p = reinterpret_cast<const float4*>(W2S);
        float accv = 0.f;
#pragma unroll
        for (int h4 = 0; h4 < 16; h4++) {
            float4 ad = adp[h4], aw = awp[h4], swv = swp[h4], w2 = w2p[h4];
            float nf, v;
            nf = (swv.x + (ad.x - aw.x) * waj) * 0.0625f;
            v = nf > 0.f ? nf : 0.01f * nf; accv = fmaf(v, w2.x, accv);
            nf = (swv.y + (ad.y - aw.y) * waj) * 0.0625f;
            v = nf > 0.f ? nf : 0.01f * nf; accv = fmaf(v, w2.y, accv);
            nf = (swv.z + (ad.z - aw.z) * waj) * 0.0625f;
            v = nf > 0.f ? nf : 0.01f * nf; accv = fmaf(v, w2.z, accv);
            nf = (swv.w + (ad.w - aw.w) * waj) * 0.0625f;
            v = nf > 0.f ? nf : 0.01f * nf; accv = fmaf(v, w2.w, accv);
        }
        out[(b0 + sbl) * 256 + r2] = accv;         // value[b, a, j]
        if (out_size >= 262144)                    // weight[b, j_out=a, i_out=j]
            out[131072 + (b0 + sbl) * 256 + r2] = waj;
    }
}

extern "C" void kernel_launch(void* const* d_in, const int* in_sizes, int n_in,
                              void* d_out, int out_size) {
    const float* states   = (const float*)d_in[0];
    const float* policies = (const float*)d_in[1];
    const float* actions  = (const float*)d_in[2];
    const float* Wk       = (const float*)d_in[3];
    const float* bk       = (const float*)d_in[4];
    const float* Wq       = (const float*)d_in[5];
    const float* bq       = (const float*)d_in[6];
    const float* Wv       = (const float*)d_in[7];
    const float* bv       = (const float*)d_in[8];
    const float* W1       = (const float*)d_in[9];
    const float* W2       = (const float*)d_in[10];
    float* out = (float*)d_out;

    cudaFuncSetAttribute(aw_attn, cudaFuncAttributeMaxDynamicSharedMemorySize, DSM_BYTES);

    prep<<<48, 256>>>(Wk, Wq, Wv, W1);
    gemm_kqc<<<dim3(128, 3), 256>>>(states, bk, bq, bv);
    tails_tanh<<<256, 256>>>(actions, policies);
    aw_attn<<<256, 256, DSM_BYTES>>>(W2, out, out_size);
}

// round 13
// speedup vs baseline: 1.0087x; 1.0087x over previous
#include <cuda_runtime.h>

// ---------------------------------------------------------------------------
// ScalarDotProductCriticNetworkV8 — fused kernel, 4 batches/CTA (R13).
//
// Shapes: B=512, N=16, A=16, OBS=112, D=128, H=64, F_IN=128.
// Grid 128 x 512 threads; R10-R12 multi-kernel branch abandoned (lost to R8
// 3x). R13 = R8 logic with 4 batches per CTA: the 4 warp-groups sharing a
// weight column hit the same L1 line -> L2 miss traffic per batch halved.
// smem 129.8KB (occ 1, 16 warps/SM = same as R8), single wave.
// ---------------------------------------------------------------------------

#define ULL unsigned long long

#define PACK2(d, lo, hi) asm("mov.b64 %0, {%1, %2};" : "=l"(d) : "f"(lo), "f"(hi))
#define UNPACK2(lo, hi, v) asm("mov.b64 {%0, %1}, %2;" : "=f"(lo), "=f"(hi) : "l"(v))
#define FMA2(acc, a, b) asm("fma.rn.f32x2 %0, %1, %2, %0;" : "+l"(acc) : "l"(a), "l"(b))
#define TANHA(y, x) asm("tanh.approx.f32 %0, %1;" : "=f"(y) : "f"(x))

// Pre-transposed weights (scratch; filled by prep kernel each launch).
__device__ float g_WkT[112 * 128];   // [kk][c]
__device__ float g_WqT[112 * 128];   // [kk][c]
__device__ float g_WvT[128 * 128];   // [f][c]
__device__ float g_W1T[128 * 64];    // [d][h]

__global__ void prep_weights(const float* __restrict__ Wk, const float* __restrict__ Wq,
                             const float* __restrict__ Wv, const float* __restrict__ W1) {
    int t = blockIdx.x * blockDim.x + threadIdx.x;
    int stride = gridDim.x * blockDim.x;
    for (int i = t; i < 112 * 128; i += stride) {
        int kk = i >> 7, c = i & 127;
        g_WkT[i] = Wk[c * 112 + kk];
        g_WqT[i] = Wq[c * 112 + kk];
    }
    for (int i = t; i < 128 * 128; i += stride) {
        int f = i >> 7, c = i & 127;
        g_WvT[i] = Wv[c * 128 + f];
    }
    for (int i = t; i < 128 * 64; i += stride) {
        int d = i >> 6, h = i & 63;
        g_W1T[i] = W1[h * 128 + d];
    }
}

// Shared memory (floats). 64 rows = 4 batches x 16; transposed arrays use
// row stride 68 (272B, 16B-aligned). Two aliased regions:
//  A @0 (9792):    P0-P2: stT[112][68]@0, actT[16][68]@7616, polT[16][68]@8704
//                  P4-P5: aw1[64][68]@0, adw1[64][68]@4352
//  B @9792 (17408): P1,P3: k_s[64][128]@9792, q_s[64][132]@17984
//                   P2,P4: avoT[128][68]@9792, avdT[128][68]@18496
//  sw1[64][64]@27200, wt[64][17]@31296, w2s[64]@32384
#define OFF_STT   0
#define OFF_ACTT  7616
#define OFF_POLT  8704
#define OFF_AW1   0
#define OFF_ADW1  4352
#define OFF_K     9792
#define OFF_Q     17984
#define OFF_AVO   9792
#define OFF_AVD   18496
#define OFF_SW1   27200
#define OFF_WT    31296
#define OFF_W2    32384
#define SMEM_FLOATS 32448
#define SMEM_BYTES  (SMEM_FLOATS * 4)

__global__ void __launch_bounds__(512, 1)
critic_kernel(const float* __restrict__ states,
              const float* __restrict__ policies,
              const float* __restrict__ actions,
              const float* __restrict__ bk,
              const float* __restrict__ bq,
              const float* __restrict__ bv,
              const float* __restrict__ W2,
              float* __restrict__ out,
              int out_size) {
    extern __shared__ float sm[];
    float* stT  = sm + OFF_STT;
    float* actT = sm + OFF_ACTT;
    float* polT = sm + OFF_POLT;
    float* aw1  = sm + OFF_AW1;
    float* adw1 = sm + OFF_ADW1;
    float* k_s  = sm + OFF_K;
    float* q_s  = sm + OFF_Q;
    float* avoT = sm + OFF_AVO;
    float* avdT = sm + OFF_AVD;
    float* sw1  = sm + OFF_SW1;
    float* wt   = sm + OFF_WT;
    float* w2s  = sm + OFF_W2;

    const int t = threadIdx.x;
    const int b0 = blockIdx.x * 4;

    // ---- phase 0: load inputs (transposed; rows packed bl*16+r) ----
    {
        const float* stb = states + b0 * (16 * 112);
        for (int idx = t; idx < 64 * 112; idx += 512) {
            int rg = idx / 112, kk = idx - rg * 112;
            stT[kk * 68 + rg] = stb[idx];
        }
#pragma unroll
        for (int s = 0; s < 2; s++) {
            int idx = t + 512 * s;                 // 0..1023
            int bl = idx >> 8, rem = idx & 255, i = rem >> 4, a = rem & 15;
            actT[a * 68 + bl * 16 + i] = actions[b0 * 256 + idx];
            polT[a * 68 + bl * 16 + i] = policies[b0 * 256 + idx];
        }
        if (t < 64) w2s[t] = W2[t];
    }
    __syncthreads();

    // thread -> (column c, batch g): 16 rows each
    const int c = t & 127, g = t >> 7;             // g in 0..3
    const int rbase = g * 16;

    // ---- phase 1: k AND q for 16 rows per thread ----
    {
        ULL ka[8], qa[8];
        {
            float bkc = bk[c], bqc = bq[c];
#pragma unroll
            for (int rp = 0; rp < 8; rp++) { PACK2(ka[rp], bkc, bkc); PACK2(qa[rp], bqc, bqc); }
        }
#pragma unroll 4
        for (int kk = 0; kk < 112; kk++) {
            float wk = g_WkT[kk * 128 + c];
            float wq = g_WqT[kk * 128 + c];
            ULL wk2, wq2; PACK2(wk2, wk, wk); PACK2(wq2, wq, wq);
            const ulonglong2* sp = reinterpret_cast<const ulonglong2*>(stT + kk * 68 + rbase);
#pragma unroll
            for (int p4 = 0; p4 < 4; p4++) {
                ulonglong2 sv = sp[p4];
                FMA2(ka[2 * p4], wk2, sv.x); FMA2(ka[2 * p4 + 1], wk2, sv.y);
                FMA2(qa[2 * p4], wq2, sv.x); FMA2(qa[2 * p4 + 1], wq2, sv.y);
            }
        }
        const float s = 0.08838834764831845f;  // 1/sqrt(128)
#pragma unroll
        for (int rp = 0; rp < 8; rp++) {
            float lo, hi;
            UNPACK2(lo, hi, ka[rp]);
            k_s[(rbase + 2 * rp) * 128 + c] = lo;
            k_s[(rbase + 2 * rp + 1) * 128 + c] = hi;
            UNPACK2(lo, hi, qa[rp]);
            q_s[(rbase + 2 * rp) * 132 + c] = lo * s;
            q_s[(rbase + 2 * rp + 1) * 132 + c] = hi * s;
        }
    }
    __syncthreads();

    // ---- phase 3: scores + softmax over i (16-lane shfl groups) ----
#pragma unroll
    for (int s = 0; s < 2; s++) {
        int id = t + 512 * s;                      // 0..1023
        int sbl = id >> 8, j = (id >> 4) & 15, i = id & 15;
        const float4* qp = reinterpret_cast<const float4*>(q_s + (sbl * 16 + i) * 132);
        const float4* kp = reinterpret_cast<const float4*>(k_s + (sbl * 16 + j) * 128);
        float s0 = 0.f, s1 = 0.f, s2f = 0.f, s3 = 0.f;
#pragma unroll 8
        for (int d4 = 0; d4 < 32; d4++) {
            float4 qv = qp[d4], kv = kp[d4];
            s0 = fmaf(qv.x, kv.x, s0); s1 = fmaf(qv.y, kv.y, s1);
            s2f = fmaf(qv.z, kv.z, s2f); s3 = fmaf(qv.w, kv.w, s3);
        }
        float sc = (s0 + s1) + (s2f + s3);
        float m = sc;
#pragma unroll
        for (int o = 8; o; o >>= 1) m = fmaxf(m, __shfl_xor_sync(0xffffffffu, m, o));
        float e = __expf(sc - m);
        float sum = e;
#pragma unroll
        for (int o = 8; o; o >>= 1) sum += __shfl_xor_sync(0xffffffffu, sum, o);
        wt[(sbl * 16 + j) * 17 + i] = e / sum;
    }
    __syncthreads();

    // ---- phase 2: avoff/avdiag, shared states partial (16 rows/thread) ----
    // (avoT/avdT overwrite dead k_s/q_s)
    {
        ULL sh[8];
        {
            float bvc = bv[c];
#pragma unroll
            for (int rp = 0; rp < 8; rp++) PACK2(sh[rp], bvc, bvc);
        }
#pragma unroll 4
        for (int f = 0; f < 112; f++) {
            float w = g_WvT[f * 128 + c];
            ULL w2; PACK2(w2, w, w);
            const ulonglong2* sp = reinterpret_cast<const ulonglong2*>(stT + f * 68 + rbase);
#pragma unroll
            for (int p4 = 0; p4 < 4; p4++) {
                ulonglong2 sv = sp[p4];
                FMA2(sh[2 * p4], w2, sv.x); FMA2(sh[2 * p4 + 1], w2, sv.y);
            }
        }
        // actions tail -> avoff
        {
            ULL wk_[8];
#pragma unroll
            for (int rp = 0; rp < 8; rp++) wk_[rp] = sh[rp];
#pragma unroll 4
            for (int f = 0; f < 16; f++) {
                float w = g_WvT[(112 + f) * 128 + c];
                ULL w2; PACK2(w2, w, w);
                const ulonglong2* sp = reinterpret_cast<const ulonglong2*>(actT + f * 68 + rbase);
#pragma unroll
                for (int p4 = 0; p4 < 4; p4++) {
                    ulonglong2 sv = sp[p4];
                    FMA2(wk_[2 * p4], w2, sv.x); FMA2(wk_[2 * p4 + 1], w2, sv.y);
                }
            }
            float v[16];
#pragma unroll
            for (int rp = 0; rp < 8; rp++) {
                float lo, hi; UNPACK2(lo, hi, wk_[rp]);
                TANHA(v[2 * rp], lo); TANHA(v[2 * rp + 1], hi);
            }
            float* dst = avoT + c * 68 + rbase;
#pragma unroll
            for (int p4 = 0; p4 < 4; p4++)
                *reinterpret_cast<float4*>(dst + 4 * p4) =
                    make_float4(v[4 * p4], v[4 * p4 + 1], v[4 * p4 + 2], v[4 * p4 + 3]);
        }
        // policies tail -> avdiag
        {
            ULL wk_[8];
#pragma unroll
            for (int rp = 0; rp < 8; rp++) wk_[rp] = sh[rp];
#pragma unroll 4
            for (int f = 0; f < 16; f++) {
                float w = g_WvT[(112 + f) * 128 + c];
                ULL w2; PACK2(w2, w, w);
                const ulonglong2* sp = reinterpret_cast<const ulonglong2*>(polT + f * 68 + rbase);
#pragma unroll
                for (int p4 = 0; p4 < 4; p4++) {
                    ulonglong2 sv = sp[p4];
                    FMA2(wk_[2 * p4], w2, sv.x); FMA2(wk_[2 * p4 + 1], w2, sv.y);
                }
            }
            float v[16];
#pragma unroll
            for (int rp = 0; rp < 8; rp++) {
                float lo, hi; UNPACK2(lo, hi, wk_[rp]);
                TANHA(v[2 * rp], lo); TANHA(v[2 * rp + 1], hi);
            }
            float* dst = avdT + c * 68 + rbase;
#pragma unroll
            for (int p4 = 0; p4 < 4; p4++)
                *reinterpret_cast<float4*>(dst + 4 * p4) =
                    make_float4(v[4 * p4], v[4 * p4 + 1], v[4 * p4 + 2], v[4 * p4 + 3]);
        }
    }
    __syncthreads();

    // ---- phase 4: AW1/AdW1, 2 h-columns x 8 rows per thread ----
    // (aw1/adw1 overwrite dead stT/actT/polT)
    {
        const int h = t & 31, m = (t >> 5) & 1, rg = t >> 6;  // rg in 0..7
        const int r0 = rg * 8;
        const float* srcT = m ? avdT : avoT;
        float* dst = m ? adw1 : aw1;
        ULL a0[4] = {}, a1[4] = {};
#pragma unroll 4
        for (int d = 0; d < 128; d++) {
            float w0 = g_W1T[d * 64 + h];
            float w1 = g_W1T[d * 64 + h + 32];
            ULL w02, w12; PACK2(w02, w0, w0); PACK2(w12, w1, w1);
            const ulonglong2* sp = reinterpret_cast<const ulonglong2*>(srcT + d * 68 + r0);
            ulonglong2 sv0 = sp[0], sv1 = sp[1];
            FMA2(a0[0], w02, sv0.x); FMA2(a0[1], w02, sv0.y);
            FMA2(a0[2], w02, sv1.x); FMA2(a0[3], w02, sv1.y);
            FMA2(a1[0], w12, sv0.x); FMA2(a1[1], w12, sv0.y);
            FMA2(a1[2], w12, sv1.x); FMA2(a1[3], w12, sv1.y);
        }
#pragma unroll
        for (int rp = 0; rp < 4; rp++) {
            float lo, hi;
            UNPACK2(lo, hi, a0[rp]);
            dst[(r0 + 2 * rp) * 68 + h] = lo;
            dst[(r0 + 2 * rp + 1) * 68 + h] = hi;
            UNPACK2(lo, hi, a1[rp]);
            dst[(r0 + 2 * rp) * 68 + h + 32] = lo;
            dst[(r0 + 2 * rp + 1) * 68 + h + 32] = hi;
        }
    }
    __syncthreads();

    // ---- phase 5a: SW1[ag,h] = sum_i wt[ag,i] * AW1[blr+i,h], 8 rows/thr ----
    {
        int h = t & 63, gg = t >> 6, a0g = gg * 8;   // gg in 0..7
        int blr = (a0g >> 4) * 16;
        float acc[8] = {};
#pragma unroll
        for (int i = 0; i < 16; i++) {
            float aw_ = aw1[(blr + i) * 68 + h];
#pragma unroll
            for (int aa = 0; aa < 8; aa++)
                acc[aa] = fmaf(wt[(a0g + aa) * 17 + i], aw_, acc[aa]);
        }
#pragma unroll
        for (int aa = 0; aa < 8; aa++) sw1[(a0g + aa) * 64 + h] = acc[aa];
    }
    __syncthreads();

    // ---- phase 5b: value + weight outputs ----
#pragma unroll
    for (int s = 0; s < 2; s++) {
        int id = t + 512 * s;                      // 0..1023
        int sbl = id >> 8, r2 = id & 255;
        int a = r2 >> 4, j = r2 & 15;
        int ag = sbl * 16 + a, jg = sbl * 16 + j;
        float waj = wt[ag * 17 + j];
        const float4* adp = reinterpret_cast<const float4*>(adw1 + jg * 68);
        const float4* awp = reinterpret_cast<const float4*>(aw1 + jg * 68);
        const float4* swp = reinterpret_cast<const float4*>(sw1 + ag * 64);
        const float4* w2p = reinterpret_cast<const float4*>(w2s);
        float accv = 0.f;
#pragma unroll
        for (int h4 = 0; h4 < 16; h4++) {
            float4 ad = adp[h4], aw = awp[h4], swv = swp[h4], w2 = w2p[h4];
            float nf, v;
            nf = (swv.x + (ad.x - aw.x) * waj) * 0.0625f;
            v = nf > 0.f ? nf : 0.01f * nf; accv = fmaf(v, w2.x, accv);
            nf = (swv.y + (ad.y - aw.y) * waj) * 0.0625f;
            v = nf > 0.f ? nf : 0.01f * nf; accv = fmaf(v, w2.y, accv);
            nf = (swv.z + (ad.z - aw.z) * waj) * 0.0625f;
            v = nf > 0.f ? nf : 0.01f * nf; accv = fmaf(v, w2.z, accv);
            nf = (swv.w + (ad.w - aw.w) * waj) * 0.0625f;
            v = nf > 0.f ? nf : 0.01f * nf; accv = fmaf(v, w2.w, accv);
        }
        out[(b0 + sbl) * 256 + r2] = accv;         // value[b, a, j]
        if (out_size >= 262144)                    // weight[b, j_out=a, i_out=j] = waj
            out[131072 + (b0 + sbl) * 256 + r2] = waj;
    }
}

extern "C" void kernel_launch(void* const* d_in, const int* in_sizes, int n_in,
                              void* d_out, int out_size) {
    const float* states   = (const float*)d_in[0];
    const float* policies = (const float*)d_in[1];
    const float* actions  = (const float*)d_in[2];
    const float* Wk       = (const float*)d_in[3];
    const float* bk       = (const float*)d_in[4];
    const float* Wq       = (const float*)d_in[5];
    const float* bq       = (const float*)d_in[6];
    const float* Wv       = (const float*)d_in[7];
    const float* bv       = (const float*)d_in[8];
    const float* W1       = (const float*)d_in[9];
    const float* W2       = (const float*)d_in[10];
    float* out = (float*)d_out;

    cudaFuncSetAttribute(critic_kernel, cudaFuncAttributeMaxDynamicSharedMemorySize, SMEM_BYTES);

    prep_weights<<<48, 256>>>(Wk, Wq, Wv, W1);
    critic_kernel<<<128, 512, SMEM_BYTES>>>(states, policies, actions,
                                            bk, bq, bv, W2, out, out_size);
}